// round 4
// baseline (speedup 1.0000x reference)
#include <cuda_runtime.h>
#include <math.h>

#define NN   50000
#define EE   300000
#define TOTE (EE + NN)
#define GG   64

// ---------------- scratch (device globals; no allocation allowed) ----------
__device__ float4 g_xw4[NN * 64];   // x @ W   [N, 256] viewed as [N, 64] float4
__device__ float  g_as[NN * 2];     // <xw, att_src> per node,head
__device__ float  g_ad[NN * 2];     // <xw, att_dst> per node,head
__device__ int    g_deg[NN];        // in-degree (incl self loop)
__device__ int    g_off[NN];        // CSR offsets (stable copy)
__device__ int    g_woff[NN];       // CSR offsets (scatter cursor)
__device__ int    g_srcs[TOTE];     // sources grouped by target
__device__ float  g_z[NN * 3];      // per-node log-softmax logits

// ---------------- kernels ----------------------------------------------------
__global__ void k_init() {
    int i = blockIdx.x * blockDim.x + threadIdx.x;
    if (i < NN) g_deg[i] = 0;
}

// xw[n, col] = sum_f x[n,f] * W[f, col]  (W row-major [128, 256])
__global__ void k_gemm(const float* __restrict__ x, const float* __restrict__ W) {
    __shared__ __align__(16) float xs[8 * 128];
    int n0 = blockIdx.x * 8;
    int col = threadIdx.x;
    for (int i = threadIdx.x; i < 8 * 128; i += 256) xs[i] = x[n0 * 128 + i];
    __syncthreads();

    float acc[8] = {0, 0, 0, 0, 0, 0, 0, 0};
#pragma unroll 4
    for (int kb = 0; kb < 32; kb++) {
        float w0 = W[(kb * 4 + 0) * 256 + col];
        float w1 = W[(kb * 4 + 1) * 256 + col];
        float w2 = W[(kb * 4 + 2) * 256 + col];
        float w3 = W[(kb * 4 + 3) * 256 + col];
#pragma unroll
        for (int i = 0; i < 8; i++) {
            const float* xr = xs + i * 128 + kb * 4;
            acc[i] += xr[0] * w0;
            acc[i] += xr[1] * w1;
            acc[i] += xr[2] * w2;
            acc[i] += xr[3] * w3;
        }
    }
    float* xwf = (float*)g_xw4;
#pragma unroll
    for (int i = 0; i < 8; i++) xwf[(n0 + i) * 256 + col] = acc[i];
}

// per-node attention scalars: one warp per (node, head)
__global__ void k_asad(const float* __restrict__ att_s, const float* __restrict__ att_d) {
    int gw   = (blockIdx.x * blockDim.x + threadIdx.x) >> 5;
    int lane = threadIdx.x & 31;
    if (gw >= NN * 2) return;
    int n = gw >> 1, h = gw & 1;
    float4 v = g_xw4[n * 64 + h * 32 + lane];
    int fb = h * 128 + lane * 4;
    float s = v.x * att_s[fb] + v.y * att_s[fb + 1] + v.z * att_s[fb + 2] + v.w * att_s[fb + 3];
    float d = v.x * att_d[fb] + v.y * att_d[fb + 1] + v.z * att_d[fb + 2] + v.w * att_d[fb + 3];
#pragma unroll
    for (int off = 16; off; off >>= 1) {
        s += __shfl_down_sync(0xffffffffu, s, off);
        d += __shfl_down_sync(0xffffffffu, d, off);
    }
    if (lane == 0) { g_as[gw] = s; g_ad[gw] = d; }
}

// degree histogram of targets (int32 edge_index!)
__global__ void k_deg(const int* __restrict__ ei) {
    int e = blockIdx.x * blockDim.x + threadIdx.x;
    if (e >= TOTE) return;
    int t = (e < EE) ? ei[EE + e] : (e - EE);
    if ((unsigned)t < NN) atomicAdd(&g_deg[t], 1);
}

// one-block exclusive scan of degrees -> offsets
__global__ void k_scan() {
    __shared__ int sp[256];
    const int CH = (NN + 255) / 256;   // 196
    int t = threadIdx.x;
    int base = t * CH;
    int sum = 0;
    for (int i = 0; i < CH; i++) { int idx = base + i; if (idx < NN) sum += g_deg[idx]; }
    sp[t] = sum;
    __syncthreads();
    for (int off = 1; off < 256; off <<= 1) {
        int v = (t >= off) ? sp[t - off] : 0;
        __syncthreads();
        sp[t] += v;
        __syncthreads();
    }
    int run = (t == 0) ? 0 : sp[t - 1];
    for (int i = 0; i < CH; i++) {
        int idx = base + i;
        if (idx < NN) { g_off[idx] = run; g_woff[idx] = run; run += g_deg[idx]; }
    }
}

// scatter: sources grouped by target
__global__ void k_scatter(const int* __restrict__ ei) {
    int e = blockIdx.x * blockDim.x + threadIdx.x;
    if (e >= TOTE) return;
    int s, t;
    if (e < EE) { s = ei[e]; t = ei[EE + e]; }
    else        { s = t = e - EE; }
    if ((unsigned)t >= NN || (unsigned)s >= NN) return;
    int pos = atomicAdd(&g_woff[t], 1);
    if ((unsigned)pos < TOTE) g_srcs[pos] = s;
}

// fused: segment softmax + weighted gather + bias/relu/FC(256->3)/log_softmax
// one warp per node; each lane owns 8 consecutive columns (lanes 0-15 head0).
__global__ void k_node(const float* __restrict__ bias, const float* __restrict__ fcw,
                       const float* __restrict__ fcb) {
    int n    = (blockIdx.x * blockDim.x + threadIdx.x) >> 5;
    int lane = threadIdx.x & 31;
    if (n >= NN) return;
    int off = g_off[n], deg = g_deg[n];
    float ad0 = g_ad[2 * n], ad1 = g_ad[2 * n + 1];

    // pass A: exact segment max per head
    float m0 = -INFINITY, m1 = -INFINITY;
    for (int i = lane; i < deg; i += 32) {
        int s = g_srcs[off + i];
        float l0 = g_as[2 * s]     + ad0; l0 = l0 > 0.f ? l0 : 0.2f * l0;
        float l1 = g_as[2 * s + 1] + ad1; l1 = l1 > 0.f ? l1 : 0.2f * l1;
        m0 = fmaxf(m0, l0); m1 = fmaxf(m1, l1);
    }
#pragma unroll
    for (int o = 16; o; o >>= 1) {
        m0 = fmaxf(m0, __shfl_xor_sync(0xffffffffu, m0, o));
        m1 = fmaxf(m1, __shfl_xor_sync(0xffffffffu, m1, o));
    }

    bool head0 = lane < 16;
    float acc[8] = {0, 0, 0, 0, 0, 0, 0, 0};
    float den0 = 0.f, den1 = 0.f;

    // pass B: 32-edge chunks; exp once per edge, broadcast via shfl
    for (int i0 = 0; i0 < deg; i0 += 32) {
        int cnt = min(32, deg - i0);
        int s = 0; float ex0 = 0.f, ex1 = 0.f;
        if (lane < cnt) {
            s = g_srcs[off + i0 + lane];
            float l0 = g_as[2 * s]     + ad0; l0 = l0 > 0.f ? l0 : 0.2f * l0;
            float l1 = g_as[2 * s + 1] + ad1; l1 = l1 > 0.f ? l1 : 0.2f * l1;
            ex0 = expf(l0 - m0);
            ex1 = expf(l1 - m1);
        }
        den0 += ex0; den1 += ex1;
        for (int j = 0; j < cnt; j++) {
            int   sj = __shfl_sync(0xffffffffu, s,   j);
            float e0 = __shfl_sync(0xffffffffu, ex0, j);
            float e1 = __shfl_sync(0xffffffffu, ex1, j);
            float exj = head0 ? e0 : e1;
            const float4* xs = g_xw4 + sj * 64 + lane * 2;
            float4 v0 = xs[0], v1 = xs[1];
            acc[0] += exj * v0.x; acc[1] += exj * v0.y;
            acc[2] += exj * v0.z; acc[3] += exj * v0.w;
            acc[4] += exj * v1.x; acc[5] += exj * v1.y;
            acc[6] += exj * v1.z; acc[7] += exj * v1.w;
        }
    }
#pragma unroll
    for (int o = 16; o; o >>= 1) {
        den0 += __shfl_xor_sync(0xffffffffu, den0, o);
        den1 += __shfl_xor_sync(0xffffffffu, den1, o);
    }
    float inv = 1.f / (head0 ? den0 : den1);

    // fused epilogue: normalize + bias + relu + FC(256->3)
    int colbase = lane * 8;
    float z0 = 0.f, z1 = 0.f, z2 = 0.f;
#pragma unroll
    for (int m = 0; m < 8; m++) {
        float val = acc[m] * inv + bias[colbase + m];
        val = val > 0.f ? val : 0.f;
        int k = colbase + m;
        z0 += val * fcw[k * 3 + 0];
        z1 += val * fcw[k * 3 + 1];
        z2 += val * fcw[k * 3 + 2];
    }
#pragma unroll
    for (int o = 16; o; o >>= 1) {
        z0 += __shfl_xor_sync(0xffffffffu, z0, o);
        z1 += __shfl_xor_sync(0xffffffffu, z1, o);
        z2 += __shfl_xor_sync(0xffffffffu, z2, o);
    }
    if (lane == 0) {
        z0 += fcb[0]; z1 += fcb[1]; z2 += fcb[2];
        float mx = fmaxf(z0, fmaxf(z1, z2));
        float ls = mx + logf(expf(z0 - mx) + expf(z1 - mx) + expf(z2 - mx));
        g_z[n * 3 + 0] = z0 - ls;
        g_z[n * 3 + 1] = z1 - ls;
        g_z[n * 3 + 2] = z2 - ls;
    }
}

// deterministic pool: batch is sorted -> contiguous node range per graph.
__global__ void k_pool(const int* __restrict__ batch, const float* __restrict__ a,
                       float* __restrict__ out) {
    __shared__ float sz[3][256];
    int g = blockIdx.x;
    int t = threadIdx.x;
    int lo = 0, hi = NN;
    while (lo < hi) { int mid = (lo + hi) >> 1; if (batch[mid] < g) lo = mid + 1; else hi = mid; }
    int s0 = lo;
    hi = NN;
    while (lo < hi) { int mid = (lo + hi) >> 1; if (batch[mid] < g + 1) lo = mid + 1; else hi = mid; }
    int e0 = lo;

    float z0 = 0.f, z1 = 0.f, z2 = 0.f;
    for (int n = s0 + t; n < e0; n += 256) {
        z0 += g_z[n * 3 + 0];
        z1 += g_z[n * 3 + 1];
        z2 += g_z[n * 3 + 2];
    }
    sz[0][t] = z0; sz[1][t] = z1; sz[2][t] = z2;
    __syncthreads();
    for (int off = 128; off; off >>= 1) {
        if (t < off) {
            sz[0][t] += sz[0][t + off];
            sz[1][t] += sz[1][t + off];
            sz[2][t] += sz[2][t + off];
        }
        __syncthreads();
    }
    if (t == 0) {
        float sc = *a;
        float p0 = sc * sz[0][0], p1 = sc * sz[1][0], p2 = sc * sz[2][0];
        float mx = fmaxf(p0, fmaxf(p1, p2));
        float ls = mx + logf(expf(p0 - mx) + expf(p1 - mx) + expf(p2 - mx));
        out[g * 3 + 0] = p0 - ls;
        out[g * 3 + 1] = p1 - ls;
        out[g * 3 + 2] = p2 - ls;
    }
}

// ---------------- launch -----------------------------------------------------
extern "C" void kernel_launch(void* const* d_in, const int* in_sizes, int n_in,
                              void* d_out, int out_size) {
    const float* x     = (const float*)d_in[0];
    const int*   ei    = (const int*)d_in[1];     // int64 in ref -> int32 in harness
    const int*   batch = (const int*)d_in[2];     // int64 in ref -> int32 in harness
    const float* W     = (const float*)d_in[3];
    const float* att_s = (const float*)d_in[4];
    const float* att_d = (const float*)d_in[5];
    const float* bias  = (const float*)d_in[6];
    const float* fcw   = (const float*)d_in[7];
    const float* fcb   = (const float*)d_in[8];
    const float* a     = (const float*)d_in[9];
    float* out = (float*)d_out;

    k_init   <<<(NN + 255) / 256, 256>>>();
    k_gemm   <<<NN / 8, 256>>>(x, W);
    k_asad   <<<(NN * 2) / 8, 256>>>(att_s, att_d);
    k_deg    <<<(TOTE + 255) / 256, 256>>>(ei);
    k_scan   <<<1, 256>>>();
    k_scatter<<<(TOTE + 255) / 256, 256>>>(ei);
    k_node   <<<(NN + 7) / 8, 256>>>(bias, fcw, fcb);
    k_pool   <<<GG, 256>>>(batch, a, out);
}

// round 5
// speedup vs baseline: 1.5600x; 1.5600x over previous
#include <cuda_runtime.h>
#include <math.h>

#define NN   50000
#define EE   300000
#define TOTE (EE + NN)
#define GG   64
#define NB_SCAN 196   // ceil(NN/256)

// ---------------- scratch (device globals; no allocation allowed) ----------
__device__ float4 g_xw4[NN * 64];   // x @ W   [N, 256] viewed as [N, 64] float4
__device__ float  g_as[NN * 2];     // <xw, att_src> per node,head
__device__ float  g_ad[NN * 2];     // <xw, att_dst> per node,head
__device__ int    g_deg[NN];        // in-degree (incl self loop)
__device__ int    g_off[NN];        // CSR offsets
__device__ int    g_woff[NN];       // CSR scatter cursors
__device__ int    g_srcs[TOTE];     // sources grouped by target
__device__ float  g_z[NN * 3];      // per-node log-softmax logits
__device__ int    g_bsum[256];      // scan block sums

// ---------------- kernels ----------------------------------------------------
__global__ void k_init() {
    int i = blockIdx.x * blockDim.x + threadIdx.x;
    if (i < NN) g_deg[i] = 0;
}

// Tiled GEMM: 64 nodes x 256 cols per block; thread = 8 nodes x 8 cols.
// Fused epilogue computes a_s/a_d per (node, head).
// smem: xs transposed [128][68] (x), ws [32][256] (W k-chunk).
__global__ __launch_bounds__(256) void k_gemm(const float* __restrict__ x,
                                              const float* __restrict__ W,
                                              const float* __restrict__ att_s,
                                              const float* __restrict__ att_d) {
    extern __shared__ float sm[];
    float* xs = sm;                 // [128][68], xs[k*68 + node]
    float* ws = sm + 128 * 68;      // [32][256]

    int tid = threadIdx.x;
    int tx = tid & 31;              // col group: cols tx*8 .. tx*8+7
    int ty = tid >> 5;              // node group (== warp id): nodes ty*8 .. +7
    int n0 = blockIdx.x * 64;

    // load x tile transposed (zero-pad past NN)
#pragma unroll
    for (int r = 0; r < 8; r++) {
        int lin4 = r * 256 + tid;          // float4 index in 64x32
        int node = lin4 >> 5;
        int k = (lin4 & 31) * 4;
        float4 v = make_float4(0.f, 0.f, 0.f, 0.f);
        if (n0 + node < NN) v = ((const float4*)x)[(size_t)(n0 + node) * 32 + (lin4 & 31)];
        xs[(k + 0) * 68 + node] = v.x;
        xs[(k + 1) * 68 + node] = v.y;
        xs[(k + 2) * 68 + node] = v.z;
        xs[(k + 3) * 68 + node] = v.w;
    }

    float acc[8][8];
#pragma unroll
    for (int i = 0; i < 8; i++)
#pragma unroll
        for (int j = 0; j < 8; j++) acc[i][j] = 0.f;

    for (int kc = 0; kc < 4; kc++) {
        __syncthreads();
#pragma unroll
        for (int r = 0; r < 8; r++) {
            int lin4 = r * 256 + tid;
            ((float4*)ws)[lin4] = ((const float4*)W)[kc * 2048 + lin4];
        }
        __syncthreads();
#pragma unroll 8
        for (int k = 0; k < 32; k++) {
            const float* xr = &xs[(kc * 32 + k) * 68 + ty * 8];
            float4 a0 = *(const float4*)(xr);
            float4 a1 = *(const float4*)(xr + 4);
            const float* wr = &ws[k * 256 + tx * 8];
            float4 w0 = *(const float4*)(wr);
            float4 w1 = *(const float4*)(wr + 4);
            float xv[8] = {a0.x, a0.y, a0.z, a0.w, a1.x, a1.y, a1.z, a1.w};
            float wv[8] = {w0.x, w0.y, w0.z, w0.w, w1.x, w1.y, w1.z, w1.w};
#pragma unroll
            for (int i = 0; i < 8; i++)
#pragma unroll
                for (int j = 0; j < 8; j++) acc[i][j] += xv[i] * wv[j];
        }
    }

    // epilogue: store xw + fused a_s/a_d
    int head = (tx < 16) ? 0 : 1;
    float4 s0 = ((const float4*)att_s)[tx * 2];
    float4 s1 = ((const float4*)att_s)[tx * 2 + 1];
    float4 d0 = ((const float4*)att_d)[tx * 2];
    float4 d1 = ((const float4*)att_d)[tx * 2 + 1];
#pragma unroll
    for (int i = 0; i < 8; i++) {
        int node = n0 + ty * 8 + i;
        float sp = acc[i][0] * s0.x + acc[i][1] * s0.y + acc[i][2] * s0.z + acc[i][3] * s0.w
                 + acc[i][4] * s1.x + acc[i][5] * s1.y + acc[i][6] * s1.z + acc[i][7] * s1.w;
        float dp = acc[i][0] * d0.x + acc[i][1] * d0.y + acc[i][2] * d0.z + acc[i][3] * d0.w
                 + acc[i][4] * d1.x + acc[i][5] * d1.y + acc[i][6] * d1.z + acc[i][7] * d1.w;
#pragma unroll
        for (int off = 1; off < 16; off <<= 1) {
            sp += __shfl_xor_sync(0xffffffffu, sp, off);
            dp += __shfl_xor_sync(0xffffffffu, dp, off);
        }
        if (node < NN) {
            float4 o0 = make_float4(acc[i][0], acc[i][1], acc[i][2], acc[i][3]);
            float4 o1 = make_float4(acc[i][4], acc[i][5], acc[i][6], acc[i][7]);
            g_xw4[(size_t)node * 64 + tx * 2]     = o0;
            g_xw4[(size_t)node * 64 + tx * 2 + 1] = o1;
            if ((tx & 15) == 0) {
                g_as[2 * node + head] = sp;
                g_ad[2 * node + head] = dp;
            }
        }
    }
}

// degree histogram of targets
__global__ void k_deg(const int* __restrict__ ei) {
    int e = blockIdx.x * blockDim.x + threadIdx.x;
    if (e >= TOTE) return;
    int t = (e < EE) ? ei[EE + e] : (e - EE);
    if ((unsigned)t < NN) atomicAdd(&g_deg[t], 1);
}

// parallel scan, 3 stages
__global__ void k_scan1() {
    __shared__ int sp[256];
    int t = threadIdx.x;
    int i = blockIdx.x * 256 + t;
    sp[t] = (i < NN) ? g_deg[i] : 0;
    __syncthreads();
    for (int off = 128; off; off >>= 1) {
        if (t < off) sp[t] += sp[t + off];
        __syncthreads();
    }
    if (t == 0) g_bsum[blockIdx.x] = sp[0];
}

__global__ void k_scan2() {
    __shared__ int sp[256];
    int t = threadIdx.x;
    int v = (t < NB_SCAN) ? g_bsum[t] : 0;
    sp[t] = v;
    __syncthreads();
    for (int off = 1; off < 256; off <<= 1) {
        int u = (t >= off) ? sp[t - off] : 0;
        __syncthreads();
        sp[t] += u;
        __syncthreads();
    }
    g_bsum[t] = sp[t] - v;   // exclusive
}

__global__ void k_scan3() {
    __shared__ int sp[256];
    int t = threadIdx.x;
    int i = blockIdx.x * 256 + t;
    int v = (i < NN) ? g_deg[i] : 0;
    sp[t] = v;
    __syncthreads();
    for (int off = 1; off < 256; off <<= 1) {
        int u = (t >= off) ? sp[t - off] : 0;
        __syncthreads();
        sp[t] += u;
        __syncthreads();
    }
    int excl = sp[t] - v + g_bsum[blockIdx.x];
    if (i < NN) { g_off[i] = excl; g_woff[i] = excl; }
}

// scatter: sources grouped by target
__global__ void k_scatter(const int* __restrict__ ei) {
    int e = blockIdx.x * blockDim.x + threadIdx.x;
    if (e >= TOTE) return;
    int s, t;
    if (e < EE) { s = ei[e]; t = ei[EE + e]; }
    else        { s = t = e - EE; }
    if ((unsigned)t >= NN || (unsigned)s >= NN) return;
    int pos = atomicAdd(&g_woff[t], 1);
    if ((unsigned)pos < TOTE) g_srcs[pos] = s;
}

// fused: segment softmax + weighted gather + bias/relu/FC(256->3)/log_softmax
__global__ void k_node(const float* __restrict__ bias, const float* __restrict__ fcw,
                       const float* __restrict__ fcb) {
    int n    = (blockIdx.x * blockDim.x + threadIdx.x) >> 5;
    int lane = threadIdx.x & 31;
    if (n >= NN) return;
    int off = g_off[n], deg = g_deg[n];
    float ad0 = g_ad[2 * n], ad1 = g_ad[2 * n + 1];

    // pass A: leaky is monotone -> only need max over a_s[src]
    float mas0 = -INFINITY, mas1 = -INFINITY;
    for (int i = lane; i < deg; i += 32) {
        int s = g_srcs[off + i];
        mas0 = fmaxf(mas0, g_as[2 * s]);
        mas1 = fmaxf(mas1, g_as[2 * s + 1]);
    }
#pragma unroll
    for (int o = 16; o; o >>= 1) {
        mas0 = fmaxf(mas0, __shfl_xor_sync(0xffffffffu, mas0, o));
        mas1 = fmaxf(mas1, __shfl_xor_sync(0xffffffffu, mas1, o));
    }
    float m0 = mas0 + ad0; m0 = m0 > 0.f ? m0 : 0.2f * m0;
    float m1 = mas1 + ad1; m1 = m1 > 0.f ? m1 : 0.2f * m1;

    bool head0 = lane < 16;
    float acc[8] = {0, 0, 0, 0, 0, 0, 0, 0};
    float den0 = 0.f, den1 = 0.f;

    // pass B: 32-edge chunks; exp once per edge, broadcast via shfl
    for (int i0 = 0; i0 < deg; i0 += 32) {
        int cnt = min(32, deg - i0);
        int s = 0; float ex0 = 0.f, ex1 = 0.f;
        if (lane < cnt) {
            s = g_srcs[off + i0 + lane];
            float l0 = g_as[2 * s]     + ad0; l0 = l0 > 0.f ? l0 : 0.2f * l0;
            float l1 = g_as[2 * s + 1] + ad1; l1 = l1 > 0.f ? l1 : 0.2f * l1;
            ex0 = expf(l0 - m0);
            ex1 = expf(l1 - m1);
        }
        den0 += ex0; den1 += ex1;
        for (int j = 0; j < cnt; j++) {
            int   sj = __shfl_sync(0xffffffffu, s,   j);
            float e0 = __shfl_sync(0xffffffffu, ex0, j);
            float e1 = __shfl_sync(0xffffffffu, ex1, j);
            float exj = head0 ? e0 : e1;
            const float4* xsrc = g_xw4 + sj * 64 + lane * 2;
            float4 v0 = xsrc[0], v1 = xsrc[1];
            acc[0] += exj * v0.x; acc[1] += exj * v0.y;
            acc[2] += exj * v0.z; acc[3] += exj * v0.w;
            acc[4] += exj * v1.x; acc[5] += exj * v1.y;
            acc[6] += exj * v1.z; acc[7] += exj * v1.w;
        }
    }
#pragma unroll
    for (int o = 16; o; o >>= 1) {
        den0 += __shfl_xor_sync(0xffffffffu, den0, o);
        den1 += __shfl_xor_sync(0xffffffffu, den1, o);
    }
    float inv = 1.f / (head0 ? den0 : den1);

    int colbase = lane * 8;
    float z0 = 0.f, z1 = 0.f, z2 = 0.f;
#pragma unroll
    for (int m = 0; m < 8; m++) {
        float val = acc[m] * inv + bias[colbase + m];
        val = val > 0.f ? val : 0.f;
        int k = colbase + m;
        z0 += val * fcw[k * 3 + 0];
        z1 += val * fcw[k * 3 + 1];
        z2 += val * fcw[k * 3 + 2];
    }
#pragma unroll
    for (int o = 16; o; o >>= 1) {
        z0 += __shfl_xor_sync(0xffffffffu, z0, o);
        z1 += __shfl_xor_sync(0xffffffffu, z1, o);
        z2 += __shfl_xor_sync(0xffffffffu, z2, o);
    }
    if (lane == 0) {
        z0 += fcb[0]; z1 += fcb[1]; z2 += fcb[2];
        float mx = fmaxf(z0, fmaxf(z1, z2));
        float ls = mx + logf(expf(z0 - mx) + expf(z1 - mx) + expf(z2 - mx));
        g_z[n * 3 + 0] = z0 - ls;
        g_z[n * 3 + 1] = z1 - ls;
        g_z[n * 3 + 2] = z2 - ls;
    }
}

// deterministic pool: batch sorted -> contiguous node range per graph.
__global__ void k_pool(const int* __restrict__ batch, const float* __restrict__ a,
                       float* __restrict__ out) {
    __shared__ float sz[3][256];
    int g = blockIdx.x;
    int t = threadIdx.x;
    int lo = 0, hi = NN;
    while (lo < hi) { int mid = (lo + hi) >> 1; if (batch[mid] < g) lo = mid + 1; else hi = mid; }
    int s0 = lo;
    hi = NN;
    while (lo < hi) { int mid = (lo + hi) >> 1; if (batch[mid] < g + 1) lo = mid + 1; else hi = mid; }
    int e0 = lo;

    float z0 = 0.f, z1 = 0.f, z2 = 0.f;
    for (int n = s0 + t; n < e0; n += 256) {
        z0 += g_z[n * 3 + 0];
        z1 += g_z[n * 3 + 1];
        z2 += g_z[n * 3 + 2];
    }
    sz[0][t] = z0; sz[1][t] = z1; sz[2][t] = z2;
    __syncthreads();
    for (int off = 128; off; off >>= 1) {
        if (t < off) {
            sz[0][t] += sz[0][t + off];
            sz[1][t] += sz[1][t + off];
            sz[2][t] += sz[2][t + off];
        }
        __syncthreads();
    }
    if (t == 0) {
        float sc = *a;
        float p0 = sc * sz[0][0], p1 = sc * sz[1][0], p2 = sc * sz[2][0];
        float mx = fmaxf(p0, fmaxf(p1, p2));
        float ls = mx + logf(expf(p0 - mx) + expf(p1 - mx) + expf(p2 - mx));
        out[g * 3 + 0] = p0 - ls;
        out[g * 3 + 1] = p1 - ls;
        out[g * 3 + 2] = p2 - ls;
    }
}

// ---------------- launch -----------------------------------------------------
extern "C" void kernel_launch(void* const* d_in, const int* in_sizes, int n_in,
                              void* d_out, int out_size) {
    const float* x     = (const float*)d_in[0];
    const int*   ei    = (const int*)d_in[1];
    const int*   batch = (const int*)d_in[2];
    const float* W     = (const float*)d_in[3];
    const float* att_s = (const float*)d_in[4];
    const float* att_d = (const float*)d_in[5];
    const float* bias  = (const float*)d_in[6];
    const float* fcw   = (const float*)d_in[7];
    const float* fcb   = (const float*)d_in[8];
    const float* a     = (const float*)d_in[9];
    float* out = (float*)d_out;

    const int SMEM = (128 * 68 + 32 * 256) * 4;   // 67584 B
    cudaFuncSetAttribute(k_gemm, cudaFuncAttributeMaxDynamicSharedMemorySize, SMEM);

    k_init   <<<(NN + 255) / 256, 256>>>();
    k_gemm   <<<(NN + 63) / 64, 256, SMEM>>>(x, W, att_s, att_d);
    k_deg    <<<(TOTE + 255) / 256, 256>>>(ei);
    k_scan1  <<<NB_SCAN, 256>>>();
    k_scan2  <<<1, 256>>>();
    k_scan3  <<<NB_SCAN, 256>>>();
    k_scatter<<<(TOTE + 255) / 256, 256>>>(ei);
    k_node   <<<(NN + 7) / 8, 256>>>(bias, fcw, fcb);
    k_pool   <<<GG, 256>>>(batch, a, out);
}